// round 16
// baseline (speedup 1.0000x reference)
#include <cuda_runtime.h>
#include <cstdint>

// idf-weighted masked mean pooling with active-token compaction + TMA bulk pipeline.
//   out[b,d] = sum_{l active} hidden[b,l,d] * idf[ids[b,l]] / max(nact, 1e-9)
// mask ~ Bernoulli(0.5): only active 3072B rows are fetched (~640 MB total).
// R16 = R15 (3-stage x 12KB ring) + SoA compacted list (one LDS.128 per chunk
// for weights/indices) + early empty-arrive right after the data LDS.
#define B_SZ      4096
#define L_SZ      100
#define D_SZ      768
#define CONS      192                 // consumer threads = D/4 float4 lanes
#define CWARPS    (CONS / 32)         // 6 consumer warps
#define THREADS   224                 // +1 producer warp
#define ROW_BYTES (D_SZ * 4)          // 3072
#define STAGES    3
#define CHUNK_ROWS 4
#define CHUNK_BYTES (ROW_BYTES * CHUNK_ROWS)  // 12288
#define NPAD_MAX  104                 // L_SZ padded to multiple of 4

static __device__ __forceinline__ uint32_t smem_u32(const void* p) {
    uint32_t a;
    asm("{ .reg .u64 t; cvta.to.shared.u64 t, %1; cvt.u32.u64 %0, t; }"
        : "=r"(a) : "l"(p));
    return a;
}
static __device__ __forceinline__ void mbar_init(uint32_t a, uint32_t n) {
    asm volatile("mbarrier.init.shared.b64 [%0], %1;" :: "r"(a), "r"(n) : "memory");
}
static __device__ __forceinline__ void mbar_expect_tx(uint32_t a, uint32_t bytes) {
    asm volatile("mbarrier.arrive.expect_tx.shared.b64 _, [%0], %1;"
                 :: "r"(a), "r"(bytes) : "memory");
}
static __device__ __forceinline__ void mbar_arrive(uint32_t a) {
    asm volatile("mbarrier.arrive.release.cta.shared::cta.b64 _, [%0];"
                 :: "r"(a) : "memory");
}
static __device__ __forceinline__ void mbar_wait_acq(uint32_t a, uint32_t ph) {
    asm volatile(
        "{\n\t.reg .pred P;\n\t"
        "W%=:\n\t"
        "mbarrier.try_wait.parity.acquire.cta.shared::cta.b64 P, [%0], %1, 0x989680;\n\t"
        "@P bra.uni D%=;\n\t"
        "bra.uni W%=;\n\t"
        "D%=:\n\t}"
        :: "r"(a), "r"(ph) : "memory");
}
static __device__ __forceinline__ void mbar_wait_rlx(uint32_t a, uint32_t ph) {
    asm volatile(
        "{\n\t.reg .pred P;\n\t"
        "W%=:\n\t"
        "mbarrier.try_wait.parity.relaxed.cta.shared::cta.b64 P, [%0], %1, 0x989680;\n\t"
        "@P bra.uni D%=;\n\t"
        "bra.uni W%=;\n\t"
        "D%=:\n\t}"
        :: "r"(a), "r"(ph) : "memory");
}
static __device__ __forceinline__ void bulk_g2s(uint32_t dst, const void* src,
                                                uint32_t bytes, uint32_t mbar) {
    asm volatile(
        "cp.async.bulk.shared::cta.global.mbarrier::complete_tx::bytes [%0], [%1], %2, [%3];"
        :: "r"(dst), "l"(src), "r"(bytes), "r"(mbar) : "memory");
}

__global__ __launch_bounds__(THREADS)
void sbert_idf_pool_kernel(const float* __restrict__ hidden,
                           const int*   __restrict__ ids,
                           const int*   __restrict__ mask,
                           const float* __restrict__ idf,
                           float*       __restrict__ out) {
    __shared__ alignas(16) char     ring[STAGES][CHUNK_BYTES];
    __shared__ alignas(16) int      sidx[NPAD_MAX];  // compacted token indices
    __shared__ alignas(16) float    sw[NPAD_MAX];    // compacted weights
    __shared__ unsigned             sbal[4];
    __shared__ alignas(8) uint64_t  mb_full[STAGES];
    __shared__ alignas(8) uint64_t  mb_empty[STAGES];

    const int b    = blockIdx.x;
    const int tid  = threadIdx.x;
    const int wid  = tid >> 5;
    const int lane = tid & 31;

    const uint32_t ring0  = smem_u32(ring);
    const uint32_t full0  = smem_u32(mb_full);
    const uint32_t empty0 = smem_u32(mb_empty);

    // ---- init barriers + pad entries --------------------------------------
    if (tid < STAGES) {
        mbar_init(full0  + tid * 8, 1);        // producer expect_tx arrive
        mbar_init(empty0 + tid * 8, CWARPS);   // one elected arrive per warp
    }
    if (tid < NPAD_MAX) { sidx[tid] = 0; sw[tid] = 0.0f; }

    // ---- per-token gather -------------------------------------------------
    int   m = 0;
    float w = 0.0f;
    if (tid < L_SZ) {
        m = __ldg(&mask[b * L_SZ + tid]);
        if (m != 0) w = __ldg(&idf[__ldg(&ids[b * L_SZ + tid])]);
    }
    const unsigned act = __ballot_sync(0xffffffffu, m != 0);
    if (wid < 4 && lane == 0) sbal[wid] = act;
    __syncthreads();

    const unsigned b0 = sbal[0], b1 = sbal[1], b2 = sbal[2], b3 = sbal[3];
    const int nact = __popc(b0) + __popc(b1) + __popc(b2) + __popc(b3);

    // ---- compaction: active tokens -> sidx/sw (SoA) ------------------------
    if (m != 0) {
        int pos = __popc(act & ((1u << lane) - 1u));
        if (wid >= 1) pos += __popc(b0);
        if (wid >= 2) pos += __popc(b1);
        if (wid >= 3) pos += __popc(b2);
        sidx[pos] = tid;
        sw[pos]   = w;
    }
    __syncthreads();                          // compaction visible

    // pad tail with a duplicate of the last active row (weight 0): the dup
    // fetch hits L2 (same chunk) instead of costing DRAM.
    const int npad = (nact + 3) & ~3;
    if (tid == 0 && nact > 0) {
        const int last = sidx[nact - 1];
        for (int pos = nact; pos < npad; ++pos) { sidx[pos] = last; sw[pos] = 0.0f; }
    }
    __syncthreads();                          // pads visible

    const int nchunks = npad / CHUNK_ROWS;

    // ---- producer: one thread streams 4-row chunks via TMA bulk copies ----
    if (tid == CONS) {
        const char* hb = (const char*)hidden + (long long)b * (L_SZ * ROW_BYTES);
        const int4* sidx4 = reinterpret_cast<const int4*>(sidx);
        int s = 0, ph = 1;                    // first empty-wait passes
        for (int c = 0; c < nchunks; ++c) {
            const int4 t4 = sidx4[c];         // one LDS.128: 4 token indices
            mbar_wait_rlx(empty0 + s * 8, (uint32_t)ph);
            const uint32_t fb = full0 + s * 8;
            mbar_expect_tx(fb, CHUNK_BYTES);
            const uint32_t dst = ring0 + s * CHUNK_BYTES;
            bulk_g2s(dst + 0 * ROW_BYTES, hb + (long long)t4.x * ROW_BYTES, ROW_BYTES, fb);
            bulk_g2s(dst + 1 * ROW_BYTES, hb + (long long)t4.y * ROW_BYTES, ROW_BYTES, fb);
            bulk_g2s(dst + 2 * ROW_BYTES, hb + (long long)t4.z * ROW_BYTES, ROW_BYTES, fb);
            bulk_g2s(dst + 3 * ROW_BYTES, hb + (long long)t4.w * ROW_BYTES, ROW_BYTES, fb);
            if (++s == STAGES) { s = 0; ph ^= 1; }
        }
    }

    // ---- consumers: wait-full -> 4x LDS.128 -> early arrive -> FMA --------
    if (tid < CONS) {
        const float inv = 1.0f / fmaxf((float)nact, 1e-9f);
        const char*   lane_base = &ring[0][0] + tid * 16;
        const float4* sw4       = reinterpret_cast<const float4*>(sw);

        float4 a0 = make_float4(0.f, 0.f, 0.f, 0.f);
        float4 a1 = a0, a2 = a0, a3 = a0;

        int s = 0, ph = 0;
        for (int c = 0; c < nchunks; ++c) {
            const float4 wv = sw4[c];         // one LDS.128: 4 chunk weights
            mbar_wait_acq(full0 + s * 8, (uint32_t)ph);
            const char* p = lane_base + s * CHUNK_BYTES;
            const float4 g0 = *(const float4*)(p + 0 * ROW_BYTES);
            const float4 g1 = *(const float4*)(p + 1 * ROW_BYTES);
            const float4 g2 = *(const float4*)(p + 2 * ROW_BYTES);
            const float4 g3 = *(const float4*)(p + 3 * ROW_BYTES);
            __syncwarp();                            // all lanes' reads done
            if (lane == 0) mbar_arrive(empty0 + s * 8);   // early stage release

            a0.x = fmaf(g0.x, wv.x, a0.x); a0.y = fmaf(g0.y, wv.x, a0.y);
            a0.z = fmaf(g0.z, wv.x, a0.z); a0.w = fmaf(g0.w, wv.x, a0.w);
            a1.x = fmaf(g1.x, wv.y, a1.x); a1.y = fmaf(g1.y, wv.y, a1.y);
            a1.z = fmaf(g1.z, wv.y, a1.z); a1.w = fmaf(g1.w, wv.y, a1.w);
            a2.x = fmaf(g2.x, wv.z, a2.x); a2.y = fmaf(g2.y, wv.z, a2.y);
            a2.z = fmaf(g2.z, wv.z, a2.z); a2.w = fmaf(g2.w, wv.z, a2.w);
            a3.x = fmaf(g3.x, wv.w, a3.x); a3.y = fmaf(g3.y, wv.w, a3.y);
            a3.z = fmaf(g3.z, wv.w, a3.z); a3.w = fmaf(g3.w, wv.w, a3.w);

            if (++s == STAGES) { s = 0; ph ^= 1; }
        }

        float4 r;
        r.x = (a0.x + a1.x + a2.x + a3.x) * inv;
        r.y = (a0.y + a1.y + a2.y + a3.y) * inv;
        r.z = (a0.z + a1.z + a2.z + a3.z) * inv;
        r.w = (a0.w + a1.w + a2.w + a3.w) * inv;

        reinterpret_cast<float4*>(out)[b * (D_SZ / 4) + tid] = r;
    }
}

extern "C" void kernel_launch(void* const* d_in, const int* in_sizes, int n_in,
                              void* d_out, int out_size) {
    const float* hidden = (const float*)d_in[0];
    const int*   ids    = (const int*)  d_in[1];
    const int*   mask   = (const int*)  d_in[2];
    const float* idf    = (const float*)d_in[3];
    float*       out    = (float*)d_out;

    sbert_idf_pool_kernel<<<B_SZ, THREADS>>>(hidden, ids, mask, idf, out);
}

// round 17
// speedup vs baseline: 1.0201x; 1.0201x over previous
#include <cuda_runtime.h>
#include <cstdint>

// idf-weighted masked mean pooling with active-token compaction + TMA bulk pipeline.
//   out[b,d] = sum_{l active} hidden[b,l,d] * idf[ids[b,l]] / max(nact, 1e-9)
// mask ~ Bernoulli(0.5): only active 3072B rows are fetched (~640 MB total).
// R17 = R15 control flow (late arrive, nothing live across the wait) + SoA
// compacted lists with single LDS.128 for weights/indices issued AFTER the wait.
#define B_SZ      4096
#define L_SZ      100
#define D_SZ      768
#define CONS      192                 // consumer threads = D/4 float4 lanes
#define CWARPS    (CONS / 32)         // 6 consumer warps
#define THREADS   224                 // +1 producer warp
#define ROW_BYTES (D_SZ * 4)          // 3072
#define STAGES    3
#define CHUNK_ROWS 4
#define CHUNK_BYTES (ROW_BYTES * CHUNK_ROWS)  // 12288
#define NPAD_MAX  104                 // L_SZ padded to multiple of 4

static __device__ __forceinline__ uint32_t smem_u32(const void* p) {
    uint32_t a;
    asm("{ .reg .u64 t; cvta.to.shared.u64 t, %1; cvt.u32.u64 %0, t; }"
        : "=r"(a) : "l"(p));
    return a;
}
static __device__ __forceinline__ void mbar_init(uint32_t a, uint32_t n) {
    asm volatile("mbarrier.init.shared.b64 [%0], %1;" :: "r"(a), "r"(n) : "memory");
}
static __device__ __forceinline__ void mbar_expect_tx(uint32_t a, uint32_t bytes) {
    asm volatile("mbarrier.arrive.expect_tx.shared.b64 _, [%0], %1;"
                 :: "r"(a), "r"(bytes) : "memory");
}
static __device__ __forceinline__ void mbar_arrive(uint32_t a) {
    asm volatile("mbarrier.arrive.release.cta.shared::cta.b64 _, [%0];"
                 :: "r"(a) : "memory");
}
static __device__ __forceinline__ void mbar_wait_acq(uint32_t a, uint32_t ph) {
    asm volatile(
        "{\n\t.reg .pred P;\n\t"
        "W%=:\n\t"
        "mbarrier.try_wait.parity.acquire.cta.shared::cta.b64 P, [%0], %1, 0x989680;\n\t"
        "@P bra.uni D%=;\n\t"
        "bra.uni W%=;\n\t"
        "D%=:\n\t}"
        :: "r"(a), "r"(ph) : "memory");
}
static __device__ __forceinline__ void mbar_wait_rlx(uint32_t a, uint32_t ph) {
    asm volatile(
        "{\n\t.reg .pred P;\n\t"
        "W%=:\n\t"
        "mbarrier.try_wait.parity.relaxed.cta.shared::cta.b64 P, [%0], %1, 0x989680;\n\t"
        "@P bra.uni D%=;\n\t"
        "bra.uni W%=;\n\t"
        "D%=:\n\t}"
        :: "r"(a), "r"(ph) : "memory");
}
static __device__ __forceinline__ void bulk_g2s(uint32_t dst, const void* src,
                                                uint32_t bytes, uint32_t mbar) {
    asm volatile(
        "cp.async.bulk.shared::cta.global.mbarrier::complete_tx::bytes [%0], [%1], %2, [%3];"
        :: "r"(dst), "l"(src), "r"(bytes), "r"(mbar) : "memory");
}

__global__ __launch_bounds__(THREADS)
void sbert_idf_pool_kernel(const float* __restrict__ hidden,
                           const int*   __restrict__ ids,
                           const int*   __restrict__ mask,
                           const float* __restrict__ idf,
                           float*       __restrict__ out) {
    __shared__ alignas(16) char     ring[STAGES][CHUNK_BYTES];
    __shared__ alignas(16) int      sidx[NPAD_MAX];  // compacted token indices
    __shared__ alignas(16) float    sw[NPAD_MAX];    // compacted weights
    __shared__ unsigned             sbal[4];
    __shared__ alignas(8) uint64_t  mb_full[STAGES];
    __shared__ alignas(8) uint64_t  mb_empty[STAGES];

    const int b    = blockIdx.x;
    const int tid  = threadIdx.x;
    const int wid  = tid >> 5;
    const int lane = tid & 31;

    const uint32_t ring0  = smem_u32(ring);
    const uint32_t full0  = smem_u32(mb_full);
    const uint32_t empty0 = smem_u32(mb_empty);

    // ---- init barriers + pad entries --------------------------------------
    if (tid < STAGES) {
        mbar_init(full0  + tid * 8, 1);        // producer expect_tx arrive
        mbar_init(empty0 + tid * 8, CWARPS);   // one elected arrive per warp
    }
    if (tid < NPAD_MAX) { sidx[tid] = 0; sw[tid] = 0.0f; }

    // ---- per-token gather -------------------------------------------------
    int   m = 0;
    float w = 0.0f;
    if (tid < L_SZ) {
        m = __ldg(&mask[b * L_SZ + tid]);
        if (m != 0) w = __ldg(&idf[__ldg(&ids[b * L_SZ + tid])]);
    }
    const unsigned act = __ballot_sync(0xffffffffu, m != 0);
    if (wid < 4 && lane == 0) sbal[wid] = act;
    __syncthreads();

    const unsigned b0 = sbal[0], b1 = sbal[1], b2 = sbal[2], b3 = sbal[3];
    const int nact = __popc(b0) + __popc(b1) + __popc(b2) + __popc(b3);

    // ---- compaction: active tokens -> sidx/sw (SoA) ------------------------
    if (m != 0) {
        int pos = __popc(act & ((1u << lane) - 1u));
        if (wid >= 1) pos += __popc(b0);
        if (wid >= 2) pos += __popc(b1);
        if (wid >= 3) pos += __popc(b2);
        sidx[pos] = tid;
        sw[pos]   = w;
    }
    __syncthreads();                          // compaction visible

    // pad tail with a duplicate of the last active row (weight 0): the dup
    // fetch hits L2 (same chunk) instead of costing DRAM.
    const int npad = (nact + 3) & ~3;
    if (tid == 0 && nact > 0) {
        const int last = sidx[nact - 1];
        for (int pos = nact; pos < npad; ++pos) { sidx[pos] = last; sw[pos] = 0.0f; }
    }
    __syncthreads();                          // pads visible

    const int nchunks = npad / CHUNK_ROWS;

    // ---- producer: one thread streams 4-row chunks via TMA bulk copies ----
    if (tid == CONS) {
        const char* hb = (const char*)hidden + (long long)b * (L_SZ * ROW_BYTES);
        const int4* sidx4 = reinterpret_cast<const int4*>(sidx);
        int s = 0, ph = 1;                    // first empty-wait passes
        for (int c = 0; c < nchunks; ++c) {
            mbar_wait_rlx(empty0 + s * 8, (uint32_t)ph);
            const int4 t4 = sidx4[c];         // one LDS.128: 4 token indices
            const uint32_t fb = full0 + s * 8;
            mbar_expect_tx(fb, CHUNK_BYTES);
            const uint32_t dst = ring0 + s * CHUNK_BYTES;
            bulk_g2s(dst + 0 * ROW_BYTES, hb + (long long)t4.x * ROW_BYTES, ROW_BYTES, fb);
            bulk_g2s(dst + 1 * ROW_BYTES, hb + (long long)t4.y * ROW_BYTES, ROW_BYTES, fb);
            bulk_g2s(dst + 2 * ROW_BYTES, hb + (long long)t4.z * ROW_BYTES, ROW_BYTES, fb);
            bulk_g2s(dst + 3 * ROW_BYTES, hb + (long long)t4.w * ROW_BYTES, ROW_BYTES, fb);
            if (++s == STAGES) { s = 0; ph ^= 1; }
        }
    }

    // ---- consumers: wait-full -> LDS (weights + 4 rows) -> FMA -> arrive --
    if (tid < CONS) {
        const float inv = 1.0f / fmaxf((float)nact, 1e-9f);
        const char*   lane_base = &ring[0][0] + tid * 16;
        const float4* sw4       = reinterpret_cast<const float4*>(sw);

        float4 a0 = make_float4(0.f, 0.f, 0.f, 0.f);
        float4 a1 = a0, a2 = a0, a3 = a0;

        int s = 0, ph = 0;
        for (int c = 0; c < nchunks; ++c) {
            mbar_wait_acq(full0 + s * 8, (uint32_t)ph);
            const float4 wv = sw4[c];         // one LDS.128: 4 chunk weights
            const char* p = lane_base + s * CHUNK_BYTES;
            const float4 g0 = *(const float4*)(p + 0 * ROW_BYTES);
            const float4 g1 = *(const float4*)(p + 1 * ROW_BYTES);
            const float4 g2 = *(const float4*)(p + 2 * ROW_BYTES);
            const float4 g3 = *(const float4*)(p + 3 * ROW_BYTES);

            a0.x = fmaf(g0.x, wv.x, a0.x); a0.y = fmaf(g0.y, wv.x, a0.y);
            a0.z = fmaf(g0.z, wv.x, a0.z); a0.w = fmaf(g0.w, wv.x, a0.w);
            a1.x = fmaf(g1.x, wv.y, a1.x); a1.y = fmaf(g1.y, wv.y, a1.y);
            a1.z = fmaf(g1.z, wv.y, a1.z); a1.w = fmaf(g1.w, wv.y, a1.w);
            a2.x = fmaf(g2.x, wv.z, a2.x); a2.y = fmaf(g2.y, wv.z, a2.y);
            a2.z = fmaf(g2.z, wv.z, a2.z); a2.w = fmaf(g2.w, wv.z, a2.w);
            a3.x = fmaf(g3.x, wv.w, a3.x); a3.y = fmaf(g3.y, wv.w, a3.y);
            a3.z = fmaf(g3.z, wv.w, a3.z); a3.w = fmaf(g3.w, wv.w, a3.w);

            __syncwarp();                            // all lanes' reads done
            if (lane == 0) mbar_arrive(empty0 + s * 8);
            if (++s == STAGES) { s = 0; ph ^= 1; }
        }

        float4 r;
        r.x = (a0.x + a1.x + a2.x + a3.x) * inv;
        r.y = (a0.y + a1.y + a2.y + a3.y) * inv;
        r.z = (a0.z + a1.z + a2.z + a3.z) * inv;
        r.w = (a0.w + a1.w + a2.w + a3.w) * inv;

        reinterpret_cast<float4*>(out)[b * (D_SZ / 4) + tid] = r;
    }
}

extern "C" void kernel_launch(void* const* d_in, const int* in_sizes, int n_in,
                              void* d_out, int out_size) {
    const float* hidden = (const float*)d_in[0];
    const int*   ids    = (const int*)  d_in[1];
    const int*   mask   = (const int*)  d_in[2];
    const float* idf    = (const float*)d_in[3];
    float*       out    = (float*)d_out;

    sbert_idf_pool_kernel<<<B_SZ, THREADS>>>(hidden, ids, mask, idf, out);
}